// round 16
// baseline (speedup 1.0000x reference)
#include <cuda_runtime.h>
#include <cuda_fp16.h>
#include <cstdint>
#include <math.h>

#define DIM 256
#define TM 64
#define THREADS 256
#define NJOBS 32                  // 4 passes x 8 chunks (KC=32)

#define XINP 32768                // per-input X region: 64 rows x 512 B (swizzled)
#define WOFF 65536                // = 2*XINP
#define WBUF 16384                // 256 n x 64 B (swizzled)
#define SMEM_BYTES (WOFF + 3 * WBUF)   // 114688 -> 2 CTAs/SM

__device__ __half g_W[4][DIM * DIM];   // [n][k] transposed fp16

__device__ __forceinline__ uint32_t smem_u32(const void* p) {
    uint32_t a;
    asm("{ .reg .u64 t; cvta.to.shared.u64 t, %1; cvt.u32.u64 %0, t; }" : "=r"(a) : "l"(p));
    return a;
}
__device__ __forceinline__ void cp16(uint32_t s, const void* g) {
    asm volatile("cp.async.cg.shared.global [%0], [%1], 16;" :: "r"(s), "l"(g));
}
#define CP_COMMIT() asm volatile("cp.async.commit_group;" ::: "memory")
#define CP_WAIT(n)  asm volatile("cp.async.wait_group %0;" :: "n"(n) : "memory")
#define PAIR_BAR(id) asm volatile("bar.sync %0, 64;" :: "r"(id) : "memory")

__device__ __forceinline__ void ldsm4(uint32_t* r, uint32_t addr) {
    asm volatile("ldmatrix.sync.aligned.m8n8.x4.shared.b16 {%0,%1,%2,%3}, [%4];"
                 : "=r"(r[0]), "=r"(r[1]), "=r"(r[2]), "=r"(r[3]) : "r"(addr));
}
__device__ __forceinline__ void mma16(float* c, const uint32_t* a, const uint32_t* b) {
    asm volatile(
        "mma.sync.aligned.m16n8k16.row.col.f32.f16.f16.f32 "
        "{%0,%1,%2,%3}, {%4,%5,%6,%7}, {%8,%9}, {%0,%1,%2,%3};"
        : "+f"(c[0]), "+f"(c[1]), "+f"(c[2]), "+f"(c[3])
        : "r"(a[0]), "r"(a[1]), "r"(a[2]), "r"(a[3]), "r"(b[0]), "r"(b[1]));
}

__device__ __forceinline__ void zero_acc(float (&acc)[2][8][4]) {
#pragma unroll
    for (int mt = 0; mt < 2; ++mt)
#pragma unroll
        for (int nt = 0; nt < 8; ++nt)
#pragma unroll
            for (int q = 0; q < 4; ++q) acc[mt][nt][q] = 0.f;
}

// one k16 step of the 32x64 warptile
__device__ __forceinline__ void k16_step(uint32_t abase, uint32_t bbase,
                                         uint32_t ua_unit, uint32_t ub_unit,
                                         float (&acc)[2][8][4]) {
    uint32_t ua[2][4];
    ldsm4(ua[0], abase + ua_unit);
    ldsm4(ua[1], abase + 16 * 512 + ua_unit);
#pragma unroll
    for (int nt2 = 0; nt2 < 4; ++nt2) {
        uint32_t b[4];
        ldsm4(b, bbase + nt2 * 1024 + ub_unit);
        mma16(acc[0][2 * nt2],     ua[0], b);
        mma16(acc[1][2 * nt2],     ua[1], b);
        mma16(acc[0][2 * nt2 + 1], ua[0], b + 2);
        mma16(acc[1][2 * nt2 + 1], ua[1], b + 2);
    }
}

// rowdot(acc, X_smem swizzled) -> fp16 partials in s_g[wn]
__device__ __forceinline__ void gate_dot(const char* __restrict__ Xs,
                                         const float (&acc)[2][8][4],
                                         int wm, int wn, int lq, int lr,
                                         __half (*s_g)[TM]) {
    float pr[2][2] = {{0.f, 0.f}, {0.f, 0.f}};
#pragma unroll
    for (int mt = 0; mt < 2; ++mt) {
        const int r0 = wm * 32 + mt * 16 + lq;
#pragma unroll
        for (int nt = 0; nt < 8; ++nt) {
            const uint32_t unit = (uint32_t)(((wn * 8 + nt) ^ lq) << 4) + lr * 4;
            float2 v0 = __half22float2(*reinterpret_cast<const __half2*>(Xs + r0 * 512 + unit));
            float2 v1 = __half22float2(*reinterpret_cast<const __half2*>(Xs + (r0 + 8) * 512 + unit));
            pr[mt][0] += acc[mt][nt][0] * v0.x + acc[mt][nt][1] * v0.y;
            pr[mt][1] += acc[mt][nt][2] * v1.x + acc[mt][nt][3] * v1.y;
        }
    }
#pragma unroll
    for (int off = 1; off <= 2; off <<= 1)
#pragma unroll
        for (int mt = 0; mt < 2; ++mt) {
            pr[mt][0] += __shfl_xor_sync(0xFFFFFFFFu, pr[mt][0], off);
            pr[mt][1] += __shfl_xor_sync(0xFFFFFFFFu, pr[mt][1], off);
        }
    if (lr == 0) {
#pragma unroll
        for (int mt = 0; mt < 2; ++mt) {
            s_g[wn][wm * 32 + mt * 16 + lq]     = __float2half_rn(pr[mt][0]);
            s_g[wn][wm * 32 + mt * 16 + lq + 8] = __float2half_rn(pr[mt][1]);
        }
    }
}

__global__ void __launch_bounds__(THREADS, 2)
fused_mma_kernel(const float* __restrict__ i0, const float* __restrict__ i1,
                 float* __restrict__ out) {
    extern __shared__ char dyn[];
    __shared__ __half s_g[4][TM];     // gate partials (g0 then g1)
    __shared__ __half s_sc[2][TM];    // scales s0, s1 (self-written/self-read)

    const int tid = threadIdx.x;
    const int l = tid & 31, w = tid >> 5;
    const int wm = w >> 2, wn = w & 3;            // m-split 2, n-split 4
    const int lq = l >> 2, lr = l & 3;
    const size_t rowbase = (size_t)blockIdx.x * TM;
    const uint32_t sb = smem_u32(dyn);

    // ---------- weight staging: each warp stages ITS PAIR's rows only ----------
    // warp (wm, wn) stages rows [wn*64 + wm*32, +32) -> pair-local producer/consumer
    auto stage = [&](int j) {
        const int p = j >> 3, c = j & 7;
        const __half* Bs = g_W[p];
        const uint32_t base = sb + WOFF + (uint32_t)(j % 3) * WBUF;
        const int n0 = wn * 64 + wm * 32;
#pragma unroll
        for (int t = 0; t < 4; ++t) {             // 32 rows x 64B = 2KB per warp
            const int n = n0 + t * 8 + (l >> 2);
            const int gk = l & 3;
            cp16(base + (uint32_t)(n * 64) + (uint32_t)((gk ^ ((n >> 1) & 3)) << 4),
                 Bs + n * DIM + c * 32 + gk * 8);
        }
        CP_COMMIT();
    };

    stage(0);                                     // overlap with X prologue
    stage(1);

    // ---------- prologue: LDG fp32 -> cvt -> swizzled STS fp16 ----------
#pragma unroll
    for (int s = 0; s < 2; ++s) {
        const float* src = (s ? i1 : i0) + rowbase * DIM;
        char* dst = dyn + s * XINP;
#pragma unroll
        for (int t = 0; t < 8; ++t) {
            const int id = tid + t * THREADS;
            const int r = id >> 5, cg = id & 31;
            float4 f0 = *reinterpret_cast<const float4*>(src + r * DIM + cg * 8);
            float4 f1 = *reinterpret_cast<const float4*>(src + r * DIM + cg * 8 + 4);
            __half2 h[4];
            h[0] = __floats2half2_rn(f0.x, f0.y);
            h[1] = __floats2half2_rn(f0.z, f0.w);
            h[2] = __floats2half2_rn(f1.x, f1.y);
            h[3] = __floats2half2_rn(f1.z, f1.w);
            *reinterpret_cast<uint4*>(dst + r * 512 + ((cg ^ (r & 7)) << 4)) =
                *reinterpret_cast<const uint4*>(h);
        }
    }
    __syncthreads();                              // X region visible to all warps

    // ---------- per-lane ldsm constants ----------
    const int ae = l & 7;                         // A swizzle key (row&7)
    const uint32_t a_rb = (uint32_t)((wm * 32 + (l & 7) + ((l >> 3) & 1) * 8) * 512);
    const int a_kh = (l >> 4) & 1;
    const int b_n = wn * 64 + ((l >> 4) & 1) * 8 + (l & 7);
    const uint32_t b_rb = (uint32_t)(b_n * 64);
    const int sB = (l >> 1) & 3;
    const uint32_t ub0 = (uint32_t)(((0 + ((l >> 3) & 1)) ^ sB) << 4);
    const uint32_t ub1 = (uint32_t)(((2 + ((l >> 3) & 1)) ^ sB) << 4);
    const int pair_id = 1 + wn;                   // named barrier 1..4

    float acc[2][8][4];
    zero_acc(acc);

    //  p0: A=X1,B=attn1 -> g0 dot X0   p1: A=X0,B=attn2 -> g1 dot X1
    //  p2: A=X0,B=W1 (raw)             p3: A=X1,B=W2 (raw; acc rescaled)
    for (int j = 0; j < NJOBS; ++j) {
        if (j == NJOBS - 1) { CP_WAIT(0); } else { CP_WAIT(1); }
        // CTA-wide sync only where s_g crosses pairs; else pair-local.
        if (j == 8 || j == 15 || j == 16) { __syncthreads(); }
        else                              { PAIR_BAR(pair_id); }

        if (j == 8 || j == 16) {                  // scales (self rows; dup writes benign)
            const int g = (j == 16);
#pragma unroll
            for (int mt = 0; mt < 2; ++mt)
#pragma unroll
                for (int hh = 0; hh < 2; ++hh) {
                    const int r = wm * 32 + mt * 16 + lq + hh * 8;
                    float gg = __half2float(s_g[0][r]) + __half2float(s_g[1][r])
                             + __half2float(s_g[2][r]) + __half2float(s_g[3][r]);
                    s_sc[g][r] = __float2half_rn(1.f + 1.f / (1.f + expf(-gg)));
                }
        }

        if (j + 2 < NJOBS) stage(j + 2);          // own pair slice; overlaps gemm

        const int p = j >> 3, c = j & 7;
        const int ainp = (0b1001 >> p) & 1;       // p0/p3 -> X1
        const uint32_t abase = sb + (uint32_t)ainp * XINP + a_rb;
        const uint32_t bbase = sb + WOFF + (uint32_t)(j % 3) * WBUF + b_rb;
        const int c4 = c * 4;
        const uint32_t ua0 = (uint32_t)(((c4 + 0 + a_kh) ^ ae) << 4);
        const uint32_t ua1 = (uint32_t)(((c4 + 2 + a_kh) ^ ae) << 4);
        k16_step(abase, bbase, ua0, ub0, acc);
        k16_step(abase, bbase, ua1, ub1, acc);

        if (j == 7) {                             // g0 = rowdot(U0, X0)
            gate_dot(dyn, acc, wm, wn, lq, lr, s_g);
            zero_acc(acc);
        }
        if (j == 15) {                            // g1 = rowdot(U1, X1)
            gate_dot(dyn + XINP, acc, wm, wn, lq, lr, s_g);
            zero_acc(acc);
        }
        if (j == 23) {                            // acc = P0 -> scale by s0/s1
#pragma unroll
            for (int mt = 0; mt < 2; ++mt) {
                const int r0 = wm * 32 + mt * 16 + lq;
                const float rt0 = __half2float(s_sc[0][r0]) / __half2float(s_sc[1][r0]);
                const float rt1 = __half2float(s_sc[0][r0 + 8]) / __half2float(s_sc[1][r0 + 8]);
#pragma unroll
                for (int nt = 0; nt < 8; ++nt) {
                    acc[mt][nt][0] *= rt0; acc[mt][nt][1] *= rt0;
                    acc[mt][nt][2] *= rt1; acc[mt][nt][3] *= rt1;
                }
            }
        }
    }

    // epilogue: out = s1 * acc = s0*P0 + s1*P1  (s_sc self-written rows)
#pragma unroll
    for (int mt = 0; mt < 2; ++mt) {
        const int r0 = wm * 32 + mt * 16 + lq;
        const float f0 = __half2float(s_sc[1][r0]);
        const float f1 = __half2float(s_sc[1][r0 + 8]);
#pragma unroll
        for (int nt = 0; nt < 8; ++nt) {
            const int cb = wn * 64 + nt * 8 + lr * 2;
            float2 v0 = make_float2(acc[mt][nt][0] * f0, acc[mt][nt][1] * f0);
            float2 v1 = make_float2(acc[mt][nt][2] * f1, acc[mt][nt][3] * f1);
            *reinterpret_cast<float2*>(out + (rowbase + r0) * DIM + cb) = v0;
            *reinterpret_cast<float2*>(out + (rowbase + r0 + 8) * DIM + cb) = v1;
        }
    }
}

// ---- prep: weights transposed to [n][k] fp16 ----
__global__ void wprep_kernel(const float* __restrict__ w1, const float* __restrict__ w2,
                             const float* __restrict__ a1, const float* __restrict__ a2) {
    const int z = blockIdx.x;
    const float* src = (z == 0) ? a1 : (z == 1) ? a2 : (z == 2) ? w1 : w2;
    const int n = threadIdx.x;
    const int k0 = blockIdx.y * 32;
    for (int k = k0; k < k0 + 32; ++k)
        g_W[z][n * DIM + k] = __float2half_rn(src[k * DIM + n]);
}

extern "C" void kernel_launch(void* const* d_in, const int* in_sizes, int n_in,
                              void* d_out, int out_size) {
    const float* i0 = (const float*)d_in[0];
    const float* i1 = (const float*)d_in[1];
    const float* W1 = (const float*)d_in[2];
    const float* W2 = (const float*)d_in[3];
    const float* A1 = (const float*)d_in[4];
    const float* A2 = (const float*)d_in[5];
    float* out = (float*)d_out;

    wprep_kernel<<<dim3(4, 8), 256>>>(W1, W2, A1, A2);

    cudaFuncSetAttribute(fused_mma_kernel,
                         cudaFuncAttributeMaxDynamicSharedMemorySize, SMEM_BYTES);
    const int rows = in_sizes[0] / DIM;           // 65536
    fused_mma_kernel<<<rows / TM, THREADS, SMEM_BYTES>>>(i0, i1, out);
    (void)n_in; (void)out_size;
}